// round 15
// baseline (speedup 1.0000x reference)
#include <cuda_runtime.h>
#include <cuda_fp16.h>
#include <cstdint>

#define NN 50000
#define NE 640000
#define EMB 128
#define CAP 64            // padded adjacency capacity (P(deg>=64) < 1e-30)
#define NB_TILE 391       // (NN+127)/128
#define SW 68             // smem row stride in uint32 words (64 data + 4 pad)

// ---- scratch (device globals; zero-initialized at load; degs re-zeroed per launch) ----
__device__ __half g_agg[NN * EMB];    // fp16 spmm output / gemm input (12.8 MB)
__device__ __half g_h16[NN * EMB];    // fp16 gemm output / spmm gather input (12.8 MB)
__device__ int    g_deg_src[NN];      // zeroed inside k_gemm3_head each launch
__device__ int    g_deg_dst[NN];      // doubles as placement cursor during build
__device__ int    g_colp[(size_t)NN * CAP];   // padded adjacency (12.8 MB)

// ---------------------------------------------------------------
// One-pass graph build: the dst-degree atomic IS the slot cursor.
__global__ void k_build(const int* __restrict__ src, const int* __restrict__ dst) {
    int e = (blockIdx.x * blockDim.x + threadIdx.x) * 2;
    if (e < NE) {
        int2 s = *(const int2*)(src + e);
        int2 d = *(const int2*)(dst + e);
        atomicAdd(&g_deg_src[s.x], 1);
        atomicAdd(&g_deg_src[s.y], 1);
        int p0 = atomicAdd(&g_deg_dst[d.x], 1);
        int p1 = atomicAdd(&g_deg_dst[d.y], 1);
        if (p0 < CAP) g_colp[(size_t)d.x * CAP + p0] = s.x;
        if (p1 < CAP) g_colp[(size_t)d.y * CAP + p1] = s.y;
    }
}

// ---------------------------------------------------------------
__device__ __forceinline__ uint2 pack_half4(float4 v) {
    __half2 lo = __float22half2_rn(make_float2(v.x, v.y));
    __half2 hi = __float22half2_rn(make_float2(v.z, v.w));
    uint2 r;
    r.x = *(uint32_t*)&lo;
    r.y = *(uint32_t*)&hi;
    return r;
}

// Layer-1 fused aggregate: warp per dst node. writes fp16 agg.
__global__ void __launch_bounds__(256)
k_spmm_l1(const float* __restrict__ nf, const float* __restrict__ Wemb,
          const float* __restrict__ bemb, __half* __restrict__ out) {
    __shared__ float We[512];
    __shared__ float be[128];
    int tid = threadIdx.x;
    if (tid < 256) {
        We[tid] = Wemb[tid];
        We[tid + 256] = Wemb[tid + 256];
        if (tid < 128) be[tid] = bemb[tid];
    }
    __syncthreads();

    int gw = (blockIdx.x * blockDim.x + tid) >> 5;
    int lane = tid & 31;
    if (gw >= NN) return;
    int deg = g_deg_dst[gw];
    int n = min(deg, CAP);
    const int* col = g_colp + (size_t)gw * CAP;
    float4 acc = make_float4(0.f, 0.f, 0.f, 0.f);
    float ws = 0.f;
    for (int j = lane; j < n; j += 32) {
        int s = __ldg(&col[j]);
        float w = rsqrtf((float)max(__ldg(&g_deg_src[s]), 1));
        float4 v = *(const float4*)(nf + (size_t)s * 4);
        acc.x += w * v.x; acc.y += w * v.y;
        acc.z += w * v.z; acc.w += w * v.w;
        ws += w;
    }
    #pragma unroll
    for (int o = 16; o; o >>= 1) {
        acc.x += __shfl_xor_sync(0xffffffffu, acc.x, o);
        acc.y += __shfl_xor_sync(0xffffffffu, acc.y, o);
        acc.z += __shfl_xor_sync(0xffffffffu, acc.z, o);
        acc.w += __shfl_xor_sync(0xffffffffu, acc.w, o);
        ws    += __shfl_xor_sync(0xffffffffu, ws, o);
    }
    float nd = rsqrtf((float)max(deg, 1));
    float4 o4;
    int k = lane * 4;
    o4.x = nd * (acc.x * We[k+0] + acc.y * We[128+k+0] + acc.z * We[256+k+0] + acc.w * We[384+k+0] + ws * be[k+0]);
    o4.y = nd * (acc.x * We[k+1] + acc.y * We[128+k+1] + acc.z * We[256+k+1] + acc.w * We[384+k+1] + ws * be[k+1]);
    o4.z = nd * (acc.x * We[k+2] + acc.y * We[128+k+2] + acc.z * We[256+k+2] + acc.w * We[384+k+2] + ws * be[k+2]);
    o4.w = nd * (acc.x * We[k+3] + acc.y * We[128+k+3] + acc.z * We[256+k+3] + acc.w * We[384+k+3] + ws * be[k+3]);
    *(uint2*)(out + (size_t)gw * EMB + k) = pack_half4(o4);
}

// ---------------------------------------------------------------
__device__ __forceinline__ void acc8(float* a, uint4 r) {
    float2 t;
    t = __half22float2(*(const __half2*)&r.x); a[0] += t.x; a[1] += t.y;
    t = __half22float2(*(const __half2*)&r.y); a[2] += t.x; a[3] += t.y;
    t = __half22float2(*(const __half2*)&r.z); a[4] += t.x; a[5] += t.y;
    t = __half22float2(*(const __half2*)&r.w); a[6] += t.x; a[7] += t.y;
}

// Weightless aggregation over padded adjacency: warp per dst node;
// half-warp owns an edge stream (stride 2), lane owns 8 columns (uint4).
// 4 gathers batched in flight (MLP 4) + dual accumulator sets to halve
// per-register FADD dependency chains.
__global__ void k_spmm16(const __half* __restrict__ h, __half* __restrict__ out) {
    int gw = (blockIdx.x * blockDim.x + threadIdx.x) >> 5;
    int lane = threadIdx.x & 31;
    if (gw >= NN) return;
    int deg = g_deg_dst[gw];
    int n = min(deg, CAP);
    const int* col = g_colp + (size_t)gw * CAP;
    int half = lane >> 4;
    int l = lane & 15;
    const __half* hb = h + l * 8;

    float accA[8] = {};
    float accB[8] = {};
    int j = half;
    for (; j + 6 < n; j += 8) {
        int s0 = __ldg(&col[j]);
        int s1 = __ldg(&col[j + 2]);
        int s2 = __ldg(&col[j + 4]);
        int s3 = __ldg(&col[j + 6]);
        uint4 r0 = __ldg((const uint4*)(hb + (size_t)s0 * EMB));
        uint4 r1 = __ldg((const uint4*)(hb + (size_t)s1 * EMB));
        uint4 r2 = __ldg((const uint4*)(hb + (size_t)s2 * EMB));
        uint4 r3 = __ldg((const uint4*)(hb + (size_t)s3 * EMB));
        acc8(accA, r0);
        acc8(accB, r1);
        acc8(accA, r2);
        acc8(accB, r3);
    }
    for (; j < n; j += 2) {
        int s0 = __ldg(&col[j]);
        uint4 r0 = __ldg((const uint4*)(hb + (size_t)s0 * EMB));
        acc8(accA, r0);
    }
    float acc[8];
    #pragma unroll
    for (int i = 0; i < 8; i++) {
        acc[i] = accA[i] + accB[i];
        acc[i] += __shfl_xor_sync(0xffffffffu, acc[i], 16);
    }

    if (half == 0) {
        float nd = rsqrtf((float)max(deg, 1));
        uint4 o;
        __half2 p;
        p = __float22half2_rn(make_float2(acc[0] * nd, acc[1] * nd)); o.x = *(uint32_t*)&p;
        p = __float22half2_rn(make_float2(acc[2] * nd, acc[3] * nd)); o.y = *(uint32_t*)&p;
        p = __float22half2_rn(make_float2(acc[4] * nd, acc[5] * nd)); o.z = *(uint32_t*)&p;
        p = __float22half2_rn(make_float2(acc[6] * nd, acc[7] * nd)); o.w = *(uint32_t*)&p;
        *(uint4*)(out + (size_t)gw * EMB + l * 8) = o;
    }
}

// ---------------------------------------------------------------
// fp16 tensor-core GEMM machinery (m16n8k16, fp32 accumulate).

__device__ __forceinline__ void stage_Ah(uint32_t* Ah, const __half* __restrict__ A,
                                         int row0, int M, int tid) {
    #pragma unroll
    for (int it = 0; it < 16; it++) {
        int f = tid + it * 256;
        int m = f >> 5;
        int u = f & 31;
        int gr = row0 + m;
        uint2 raw = make_uint2(0u, 0u);
        if (gr < M) raw = *(const uint2*)(A + (size_t)gr * 128 + u * 4);
        Ah[m * SW + u * 2]     = raw.x;
        Ah[m * SW + u * 2 + 1] = raw.y;
    }
}

__device__ __forceinline__ void stage_WhT(uint32_t* Wh, const float* __restrict__ W,
                                          int tid) {
    int n = tid & 127;
    int p = tid >> 7;
    #pragma unroll
    for (int w = 0; w < 32; w++) {
        int word = p * 32 + w;
        int k = word * 2;
        float lo = __ldg(&W[(size_t)k * 128 + n]);
        float hi = __ldg(&W[(size_t)(k + 1) * 128 + n]);
        __half2 hh = __float22half2_rn(make_float2(lo, hi));
        Wh[n * SW + word] = *(uint32_t*)&hh;
    }
}

__device__ __forceinline__ void mma_fullk(const uint32_t* Ah, const uint32_t* Wh,
                                          float c[2][8][4],
                                          int wm, int wn, int lg, int lt) {
    #pragma unroll
    for (int kw = 0; kw < 64; kw += 8) {
        uint32_t af[2][4];
        #pragma unroll
        for (int mt = 0; mt < 2; mt++) {
            int m = wm * 32 + mt * 16 + lg;
            const uint32_t* r0 = Ah + m * SW + kw;
            const uint32_t* r1 = Ah + (m + 8) * SW + kw;
            af[mt][0] = r0[lt];
            af[mt][1] = r1[lt];
            af[mt][2] = r0[lt + 4];
            af[mt][3] = r1[lt + 4];
        }
        #pragma unroll
        for (int nt = 0; nt < 8; nt++) {
            int n = wn * 64 + nt * 8 + lg;
            uint32_t b0 = Wh[n * SW + kw + lt];
            uint32_t b1 = Wh[n * SW + kw + 4 + lt];
            #pragma unroll
            for (int mt = 0; mt < 2; mt++) {
                asm volatile(
                    "mma.sync.aligned.m16n8k16.row.col.f32.f16.f16.f32 "
                    "{%0,%1,%2,%3}, {%4,%5,%6,%7}, {%8,%9}, {%0,%1,%2,%3};"
                    : "+f"(c[mt][nt][0]), "+f"(c[mt][nt][1]),
                      "+f"(c[mt][nt][2]), "+f"(c[mt][nt][3])
                    : "r"(af[mt][0]), "r"(af[mt][1]),
                      "r"(af[mt][2]), "r"(af[mt][3]),
                      "r"(b0), "r"(b1));
            }
        }
    }
}

// GEMM: C16[r] = rsqrt(deg_src[r]) * relu(A16 @ W + bias)[r]
__global__ void __launch_bounds__(256)
k_gemm_tc16(const __half* __restrict__ A, const float* __restrict__ W,
            const float* __restrict__ bias, __half* __restrict__ C, int M) {
    extern __shared__ uint32_t sm[];
    uint32_t* Ah = sm;
    uint32_t* Wh = sm + 128 * SW;
    int tid  = threadIdx.x;
    int warp = tid >> 5, lane = tid & 31;
    int wm = warp & 3, wn = warp >> 2;
    int lg = lane >> 2, lt = lane & 3;
    int row0 = blockIdx.x * 128;

    stage_Ah(Ah, A, row0, M, tid);
    stage_WhT(Wh, W, tid);
    __syncthreads();

    float c[2][8][4] = {};
    mma_fullk(Ah, Wh, c, wm, wn, lg, lt);

    float ns[2][2];
    #pragma unroll
    for (int mt = 0; mt < 2; mt++) {
        int r = row0 + wm * 32 + mt * 16 + lg;
        ns[mt][0] = (r < M)     ? rsqrtf((float)max(__ldg(&g_deg_src[r]), 1))     : 0.f;
        ns[mt][1] = (r + 8 < M) ? rsqrtf((float)max(__ldg(&g_deg_src[r + 8]), 1)) : 0.f;
    }

    #pragma unroll
    for (int nt = 0; nt < 8; nt++) {
        int col = wn * 64 + nt * 8 + 2 * lt;
        float2 bv = *(const float2*)(bias + col);
        #pragma unroll
        for (int mt = 0; mt < 2; mt++) {
            int r = row0 + wm * 32 + mt * 16 + lg;
            float2 o0, o1;
            o0.x = ns[mt][0] * fmaxf(c[mt][nt][0] + bv.x, 0.f);
            o0.y = ns[mt][0] * fmaxf(c[mt][nt][1] + bv.y, 0.f);
            o1.x = ns[mt][1] * fmaxf(c[mt][nt][2] + bv.x, 0.f);
            o1.y = ns[mt][1] * fmaxf(c[mt][nt][3] + bv.y, 0.f);
            if (r < M)     *(__half2*)(C + (size_t)r * 128 + col)       = __float22half2_rn(o0);
            if (r + 8 < M) *(__half2*)(C + (size_t)(r + 8) * 128 + col) = __float22half2_rn(o1);
        }
    }
}

// ---------------------------------------------------------------
// Fused layer3 + head; also re-zeroes the degree arrays for the next launch.
__global__ void __launch_bounds__(256)
k_gemm3_head(const __half* __restrict__ A, const float* __restrict__ W3,
             const float* __restrict__ b3, const float* __restrict__ Wo1,
             const float* __restrict__ bo1, const float* __restrict__ w2,
             const float* __restrict__ b2, float* __restrict__ out, int M) {
    extern __shared__ uint32_t sm[];
    uint32_t* Ah = sm;               // phase-1 A tile; reused as h tile
    uint32_t* Wh = sm + 128 * SW;    // phase-1 W3^T; reused for Wo1^T
    __shared__ float red[128];
    __shared__ float w2s[128];

    int tid  = threadIdx.x;
    int warp = tid >> 5, lane = tid & 31;
    int wm = warp & 3, wn = warp >> 2;
    int lg = lane >> 2, lt = lane & 3;
    int row0 = blockIdx.x * 128;

    if (tid < 128) {
        red[tid] = 0.f;
        w2s[tid] = w2[tid];
        int r = row0 + tid;
        if (r < NN) {
            g_deg_src[r] = 0;
            g_deg_dst[r] = 0;
        }
    }

    stage_Ah(Ah, A, row0, M, tid);
    stage_WhT(Wh, W3, tid);
    __syncthreads();
    float c[2][8][4] = {};
    mma_fullk(Ah, Wh, c, wm, wn, lg, lt);
    __syncthreads();

    #pragma unroll
    for (int nt = 0; nt < 8; nt++) {
        int col = wn * 64 + nt * 8 + 2 * lt;
        float2 bv = *(const float2*)(b3 + col);
        int widx = col >> 1;
        #pragma unroll
        for (int mt = 0; mt < 2; mt++) {
            int r = wm * 32 + mt * 16 + lg;
            __half2 h0 = __float22half2_rn(make_float2(
                fmaxf(c[mt][nt][0] + bv.x, 0.f), fmaxf(c[mt][nt][1] + bv.y, 0.f)));
            __half2 h1 = __float22half2_rn(make_float2(
                fmaxf(c[mt][nt][2] + bv.x, 0.f), fmaxf(c[mt][nt][3] + bv.y, 0.f)));
            Ah[r * SW + widx]       = *(uint32_t*)&h0;
            Ah[(r + 8) * SW + widx] = *(uint32_t*)&h1;
        }
    }
    stage_WhT(Wh, Wo1, tid);
    __syncthreads();

    float c2[2][8][4] = {};
    mma_fullk(Ah, Wh, c2, wm, wn, lg, lt);

    #pragma unroll
    for (int mt = 0; mt < 2; mt++) {
        float dot0 = 0.f, dot1 = 0.f;
        #pragma unroll
        for (int nt = 0; nt < 8; nt++) {
            int col = wn * 64 + nt * 8 + 2 * lt;
            float2 bv = *(const float2*)(bo1 + col);
            float wa = w2s[col], wb = w2s[col + 1];
            dot0 += fmaxf(c2[mt][nt][0] + bv.x, 0.f) * wa
                  + fmaxf(c2[mt][nt][1] + bv.y, 0.f) * wb;
            dot1 += fmaxf(c2[mt][nt][2] + bv.x, 0.f) * wa
                  + fmaxf(c2[mt][nt][3] + bv.y, 0.f) * wb;
        }
        int rl = wm * 32 + mt * 16 + lg;
        atomicAdd(&red[rl], dot0);
        atomicAdd(&red[rl + 8], dot1);
    }
    __syncthreads();
    if (tid < 128 && row0 + tid < M)
        out[row0 + tid] = red[tid] + b2[0];
}

// ---------------------------------------------------------------
extern "C" void kernel_launch(void* const* d_in, const int* in_sizes, int n_in,
                              void* d_out, int out_size) {
    const float* nf   = (const float*)d_in[0];
    const int*   src  = (const int*)d_in[1];
    const int*   dst  = (const int*)d_in[2];
    const float* Wemb = (const float*)d_in[3];
    const float* bemb = (const float*)d_in[4];
    const float* Wg   = (const float*)d_in[5];
    const float* bg   = (const float*)d_in[6];
    const float* Wo1  = (const float*)d_in[7];
    const float* bo1  = (const float*)d_in[8];
    const float* Wo2  = (const float*)d_in[9];
    const float* bo2  = (const float*)d_in[10];
    float* out = (float*)d_out;

    __half *agg, *h16;
    cudaGetSymbolAddress((void**)&agg, g_agg);
    cudaGetSymbolAddress((void**)&h16, g_h16);

    const int SM_GEMM = 2 * 128 * SW * 4;   // 69632 bytes
    cudaFuncSetAttribute(k_gemm_tc16,
                         cudaFuncAttributeMaxDynamicSharedMemorySize, SM_GEMM);
    cudaFuncSetAttribute(k_gemm3_head,
                         cudaFuncAttributeMaxDynamicSharedMemorySize, SM_GEMM);

    const int NB_EDGE2 = (NE / 2 + 255) / 256;   // 2 edges per thread
    const int NB_WARP = (NN * 32 + 255) / 256;   // warp-per-node kernels

    k_build<<<NB_EDGE2, 256>>>(src, dst);                       // 0

    k_spmm_l1<<<NB_WARP, 256>>>(nf, Wemb, bemb, agg);           // 1
    k_gemm_tc16<<<NB_TILE, 256, SM_GEMM>>>(agg, Wg, bg, h16, NN);        // 2

    k_spmm16<<<NB_WARP, 256>>>(h16, agg);                       // 3
    k_gemm_tc16<<<NB_TILE, 256, SM_GEMM>>>(agg, Wg + 128 * 128,
                                           bg + 128, h16, NN);  // 4
    k_spmm16<<<NB_WARP, 256>>>(h16, agg);                       // 5

    k_gemm3_head<<<NB_TILE, 256, SM_GEMM>>>(agg, Wg + 2 * 128 * 128,
                                            bg + 2 * 128, Wo1, bo1,
                                            Wo2, bo2, out, NN);  // 6
}

// round 16
// speedup vs baseline: 1.0856x; 1.0856x over previous
#include <cuda_runtime.h>
#include <cuda_fp16.h>
#include <cstdint>

#define NN 50000
#define NE 640000
#define EMB 128
#define CAP 64            // padded adjacency capacity (P(deg>=64) < 1e-30)
#define NB_TILE 391       // (NN+127)/128
#define SW 68             // smem row stride in uint32 words (64 data + 4 pad)

// ---- scratch (device globals; zero-initialized at load; degs re-zeroed per launch) ----
__device__ __half g_agg[NN * EMB];    // fp16 spmm output / gemm input (12.8 MB)
__device__ __half g_h16[NN * EMB];    // fp16 gemm output / spmm gather input (12.8 MB)
__device__ int    g_deg_src[NN];      // zeroed inside k_gemm3_head each launch
__device__ int    g_deg_dst[NN];      // doubles as placement cursor during build
__device__ int    g_colp[(size_t)NN * CAP];   // padded adjacency (12.8 MB)

// ---------------------------------------------------------------
// One-pass graph build: the dst-degree atomic IS the slot cursor.
__global__ void k_build(const int* __restrict__ src, const int* __restrict__ dst) {
    int e = (blockIdx.x * blockDim.x + threadIdx.x) * 2;
    if (e < NE) {
        int2 s = *(const int2*)(src + e);
        int2 d = *(const int2*)(dst + e);
        atomicAdd(&g_deg_src[s.x], 1);
        atomicAdd(&g_deg_src[s.y], 1);
        int p0 = atomicAdd(&g_deg_dst[d.x], 1);
        int p1 = atomicAdd(&g_deg_dst[d.y], 1);
        if (p0 < CAP) g_colp[(size_t)d.x * CAP + p0] = s.x;
        if (p1 < CAP) g_colp[(size_t)d.y * CAP + p1] = s.y;
    }
}

// ---------------------------------------------------------------
__device__ __forceinline__ uint2 pack_half4(float4 v) {
    __half2 lo = __float22half2_rn(make_float2(v.x, v.y));
    __half2 hi = __float22half2_rn(make_float2(v.z, v.w));
    uint2 r;
    r.x = *(uint32_t*)&lo;
    r.y = *(uint32_t*)&hi;
    return r;
}

// Layer-1 fused aggregate: warp per dst node. writes fp16 agg.
__global__ void __launch_bounds__(256)
k_spmm_l1(const float* __restrict__ nf, const float* __restrict__ Wemb,
          const float* __restrict__ bemb, __half* __restrict__ out) {
    __shared__ float We[512];
    __shared__ float be[128];
    int tid = threadIdx.x;
    if (tid < 256) {
        We[tid] = Wemb[tid];
        We[tid + 256] = Wemb[tid + 256];
        if (tid < 128) be[tid] = bemb[tid];
    }
    __syncthreads();

    int gw = (blockIdx.x * blockDim.x + tid) >> 5;
    int lane = tid & 31;
    if (gw >= NN) return;
    int deg = g_deg_dst[gw];
    int n = min(deg, CAP);
    const int* col = g_colp + (size_t)gw * CAP;
    float4 acc = make_float4(0.f, 0.f, 0.f, 0.f);
    float ws = 0.f;
    for (int j = lane; j < n; j += 32) {
        int s = __ldg(&col[j]);
        float w = rsqrtf((float)max(__ldg(&g_deg_src[s]), 1));
        float4 v = *(const float4*)(nf + (size_t)s * 4);
        acc.x += w * v.x; acc.y += w * v.y;
        acc.z += w * v.z; acc.w += w * v.w;
        ws += w;
    }
    #pragma unroll
    for (int o = 16; o; o >>= 1) {
        acc.x += __shfl_xor_sync(0xffffffffu, acc.x, o);
        acc.y += __shfl_xor_sync(0xffffffffu, acc.y, o);
        acc.z += __shfl_xor_sync(0xffffffffu, acc.z, o);
        acc.w += __shfl_xor_sync(0xffffffffu, acc.w, o);
        ws    += __shfl_xor_sync(0xffffffffu, ws, o);
    }
    float nd = rsqrtf((float)max(deg, 1));
    float4 o4;
    int k = lane * 4;
    o4.x = nd * (acc.x * We[k+0] + acc.y * We[128+k+0] + acc.z * We[256+k+0] + acc.w * We[384+k+0] + ws * be[k+0]);
    o4.y = nd * (acc.x * We[k+1] + acc.y * We[128+k+1] + acc.z * We[256+k+1] + acc.w * We[384+k+1] + ws * be[k+1]);
    o4.z = nd * (acc.x * We[k+2] + acc.y * We[128+k+2] + acc.z * We[256+k+2] + acc.w * We[384+k+2] + ws * be[k+2]);
    o4.w = nd * (acc.x * We[k+3] + acc.y * We[128+k+3] + acc.z * We[256+k+3] + acc.w * We[384+k+3] + ws * be[k+3]);
    *(uint2*)(out + (size_t)gw * EMB + k) = pack_half4(o4);
}

// ---------------------------------------------------------------
__device__ __forceinline__ void acc8(float* a, uint4 r) {
    float2 t;
    t = __half22float2(*(const __half2*)&r.x); a[0] += t.x; a[1] += t.y;
    t = __half22float2(*(const __half2*)&r.y); a[2] += t.x; a[3] += t.y;
    t = __half22float2(*(const __half2*)&r.z); a[4] += t.x; a[5] += t.y;
    t = __half22float2(*(const __half2*)&r.w); a[6] += t.x; a[7] += t.y;
}

// Weightless aggregation over padded adjacency: warp per dst node;
// half-warp owns an edge stream (stride 2), lane owns 8 columns (uint4).
// Per edge-pair: combine gathered rows with 4 HADD2, then widen once
// (37% fewer cvt/add ops vs per-edge widening; regs unchanged).
__global__ void k_spmm16(const __half* __restrict__ h, __half* __restrict__ out) {
    int gw = (blockIdx.x * blockDim.x + threadIdx.x) >> 5;
    int lane = threadIdx.x & 31;
    if (gw >= NN) return;
    int deg = g_deg_dst[gw];
    int n = min(deg, CAP);
    const int* col = g_colp + (size_t)gw * CAP;
    int half = lane >> 4;
    int l = lane & 15;
    const __half* hb = h + l * 8;

    float acc[8] = {};
    int j = half;
    for (; j + 2 < n; j += 4) {
        int s0 = __ldg(&col[j]);
        int s1 = __ldg(&col[j + 2]);
        uint4 r0 = __ldg((const uint4*)(hb + (size_t)s0 * EMB));
        uint4 r1 = __ldg((const uint4*)(hb + (size_t)s1 * EMB));
        __half2 p0 = __hadd2(*(const __half2*)&r0.x, *(const __half2*)&r1.x);
        __half2 p1 = __hadd2(*(const __half2*)&r0.y, *(const __half2*)&r1.y);
        __half2 p2 = __hadd2(*(const __half2*)&r0.z, *(const __half2*)&r1.z);
        __half2 p3 = __hadd2(*(const __half2*)&r0.w, *(const __half2*)&r1.w);
        float2 t;
        t = __half22float2(p0); acc[0] += t.x; acc[1] += t.y;
        t = __half22float2(p1); acc[2] += t.x; acc[3] += t.y;
        t = __half22float2(p2); acc[4] += t.x; acc[5] += t.y;
        t = __half22float2(p3); acc[6] += t.x; acc[7] += t.y;
    }
    if (j < n) {
        int s0 = __ldg(&col[j]);
        uint4 r0 = __ldg((const uint4*)(hb + (size_t)s0 * EMB));
        acc8(acc, r0);
    }
    #pragma unroll
    for (int i = 0; i < 8; i++)
        acc[i] += __shfl_xor_sync(0xffffffffu, acc[i], 16);

    if (half == 0) {
        float nd = rsqrtf((float)max(deg, 1));
        uint4 o;
        __half2 p;
        p = __float22half2_rn(make_float2(acc[0] * nd, acc[1] * nd)); o.x = *(uint32_t*)&p;
        p = __float22half2_rn(make_float2(acc[2] * nd, acc[3] * nd)); o.y = *(uint32_t*)&p;
        p = __float22half2_rn(make_float2(acc[4] * nd, acc[5] * nd)); o.z = *(uint32_t*)&p;
        p = __float22half2_rn(make_float2(acc[6] * nd, acc[7] * nd)); o.w = *(uint32_t*)&p;
        *(uint4*)(out + (size_t)gw * EMB + l * 8) = o;
    }
}

// ---------------------------------------------------------------
// fp16 tensor-core GEMM machinery (m16n8k16, fp32 accumulate).

__device__ __forceinline__ void stage_Ah(uint32_t* Ah, const __half* __restrict__ A,
                                         int row0, int M, int tid) {
    #pragma unroll
    for (int it = 0; it < 16; it++) {
        int f = tid + it * 256;
        int m = f >> 5;
        int u = f & 31;
        int gr = row0 + m;
        uint2 raw = make_uint2(0u, 0u);
        if (gr < M) raw = *(const uint2*)(A + (size_t)gr * 128 + u * 4);
        Ah[m * SW + u * 2]     = raw.x;
        Ah[m * SW + u * 2 + 1] = raw.y;
    }
}

__device__ __forceinline__ void stage_WhT(uint32_t* Wh, const float* __restrict__ W,
                                          int tid) {
    int n = tid & 127;
    int p = tid >> 7;
    #pragma unroll
    for (int w = 0; w < 32; w++) {
        int word = p * 32 + w;
        int k = word * 2;
        float lo = __ldg(&W[(size_t)k * 128 + n]);
        float hi = __ldg(&W[(size_t)(k + 1) * 128 + n]);
        __half2 hh = __float22half2_rn(make_float2(lo, hi));
        Wh[n * SW + word] = *(uint32_t*)&hh;
    }
}

__device__ __forceinline__ void mma_fullk(const uint32_t* Ah, const uint32_t* Wh,
                                          float c[2][8][4],
                                          int wm, int wn, int lg, int lt) {
    #pragma unroll
    for (int kw = 0; kw < 64; kw += 8) {
        uint32_t af[2][4];
        #pragma unroll
        for (int mt = 0; mt < 2; mt++) {
            int m = wm * 32 + mt * 16 + lg;
            const uint32_t* r0 = Ah + m * SW + kw;
            const uint32_t* r1 = Ah + (m + 8) * SW + kw;
            af[mt][0] = r0[lt];
            af[mt][1] = r1[lt];
            af[mt][2] = r0[lt + 4];
            af[mt][3] = r1[lt + 4];
        }
        #pragma unroll
        for (int nt = 0; nt < 8; nt++) {
            int n = wn * 64 + nt * 8 + lg;
            uint32_t b0 = Wh[n * SW + kw + lt];
            uint32_t b1 = Wh[n * SW + kw + 4 + lt];
            #pragma unroll
            for (int mt = 0; mt < 2; mt++) {
                asm volatile(
                    "mma.sync.aligned.m16n8k16.row.col.f32.f16.f16.f32 "
                    "{%0,%1,%2,%3}, {%4,%5,%6,%7}, {%8,%9}, {%0,%1,%2,%3};"
                    : "+f"(c[mt][nt][0]), "+f"(c[mt][nt][1]),
                      "+f"(c[mt][nt][2]), "+f"(c[mt][nt][3])
                    : "r"(af[mt][0]), "r"(af[mt][1]),
                      "r"(af[mt][2]), "r"(af[mt][3]),
                      "r"(b0), "r"(b1));
            }
        }
    }
}

// GEMM: C16[r] = rsqrt(deg_src[r]) * relu(A16 @ W + bias)[r]
__global__ void __launch_bounds__(256)
k_gemm_tc16(const __half* __restrict__ A, const float* __restrict__ W,
            const float* __restrict__ bias, __half* __restrict__ C, int M) {
    extern __shared__ uint32_t sm[];
    uint32_t* Ah = sm;
    uint32_t* Wh = sm + 128 * SW;
    int tid  = threadIdx.x;
    int warp = tid >> 5, lane = tid & 31;
    int wm = warp & 3, wn = warp >> 2;
    int lg = lane >> 2, lt = lane & 3;
    int row0 = blockIdx.x * 128;

    stage_Ah(Ah, A, row0, M, tid);
    stage_WhT(Wh, W, tid);
    __syncthreads();

    float c[2][8][4] = {};
    mma_fullk(Ah, Wh, c, wm, wn, lg, lt);

    float ns[2][2];
    #pragma unroll
    for (int mt = 0; mt < 2; mt++) {
        int r = row0 + wm * 32 + mt * 16 + lg;
        ns[mt][0] = (r < M)     ? rsqrtf((float)max(__ldg(&g_deg_src[r]), 1))     : 0.f;
        ns[mt][1] = (r + 8 < M) ? rsqrtf((float)max(__ldg(&g_deg_src[r + 8]), 1)) : 0.f;
    }

    #pragma unroll
    for (int nt = 0; nt < 8; nt++) {
        int col = wn * 64 + nt * 8 + 2 * lt;
        float2 bv = *(const float2*)(bias + col);
        #pragma unroll
        for (int mt = 0; mt < 2; mt++) {
            int r = row0 + wm * 32 + mt * 16 + lg;
            float2 o0, o1;
            o0.x = ns[mt][0] * fmaxf(c[mt][nt][0] + bv.x, 0.f);
            o0.y = ns[mt][0] * fmaxf(c[mt][nt][1] + bv.y, 0.f);
            o1.x = ns[mt][1] * fmaxf(c[mt][nt][2] + bv.x, 0.f);
            o1.y = ns[mt][1] * fmaxf(c[mt][nt][3] + bv.y, 0.f);
            if (r < M)     *(__half2*)(C + (size_t)r * 128 + col)       = __float22half2_rn(o0);
            if (r + 8 < M) *(__half2*)(C + (size_t)(r + 8) * 128 + col) = __float22half2_rn(o1);
        }
    }
}

// ---------------------------------------------------------------
// Fused layer3 + head; also re-zeroes the degree arrays for the next launch.
__global__ void __launch_bounds__(256)
k_gemm3_head(const __half* __restrict__ A, const float* __restrict__ W3,
             const float* __restrict__ b3, const float* __restrict__ Wo1,
             const float* __restrict__ bo1, const float* __restrict__ w2,
             const float* __restrict__ b2, float* __restrict__ out, int M) {
    extern __shared__ uint32_t sm[];
    uint32_t* Ah = sm;               // phase-1 A tile; reused as h tile
    uint32_t* Wh = sm + 128 * SW;    // phase-1 W3^T; reused for Wo1^T
    __shared__ float red[128];
    __shared__ float w2s[128];

    int tid  = threadIdx.x;
    int warp = tid >> 5, lane = tid & 31;
    int wm = warp & 3, wn = warp >> 2;
    int lg = lane >> 2, lt = lane & 3;
    int row0 = blockIdx.x * 128;

    if (tid < 128) {
        red[tid] = 0.f;
        w2s[tid] = w2[tid];
        int r = row0 + tid;
        if (r < NN) {
            g_deg_src[r] = 0;
            g_deg_dst[r] = 0;
        }
    }

    stage_Ah(Ah, A, row0, M, tid);
    stage_WhT(Wh, W3, tid);
    __syncthreads();
    float c[2][8][4] = {};
    mma_fullk(Ah, Wh, c, wm, wn, lg, lt);
    __syncthreads();

    #pragma unroll
    for (int nt = 0; nt < 8; nt++) {
        int col = wn * 64 + nt * 8 + 2 * lt;
        float2 bv = *(const float2*)(b3 + col);
        int widx = col >> 1;
        #pragma unroll
        for (int mt = 0; mt < 2; mt++) {
            int r = wm * 32 + mt * 16 + lg;
            __half2 h0 = __float22half2_rn(make_float2(
                fmaxf(c[mt][nt][0] + bv.x, 0.f), fmaxf(c[mt][nt][1] + bv.y, 0.f)));
            __half2 h1 = __float22half2_rn(make_float2(
                fmaxf(c[mt][nt][2] + bv.x, 0.f), fmaxf(c[mt][nt][3] + bv.y, 0.f)));
            Ah[r * SW + widx]       = *(uint32_t*)&h0;
            Ah[(r + 8) * SW + widx] = *(uint32_t*)&h1;
        }
    }
    stage_WhT(Wh, Wo1, tid);
    __syncthreads();

    float c2[2][8][4] = {};
    mma_fullk(Ah, Wh, c2, wm, wn, lg, lt);

    #pragma unroll
    for (int mt = 0; mt < 2; mt++) {
        float dot0 = 0.f, dot1 = 0.f;
        #pragma unroll
        for (int nt = 0; nt < 8; nt++) {
            int col = wn * 64 + nt * 8 + 2 * lt;
            float2 bv = *(const float2*)(bo1 + col);
            float wa = w2s[col], wb = w2s[col + 1];
            dot0 += fmaxf(c2[mt][nt][0] + bv.x, 0.f) * wa
                  + fmaxf(c2[mt][nt][1] + bv.y, 0.f) * wb;
            dot1 += fmaxf(c2[mt][nt][2] + bv.x, 0.f) * wa
                  + fmaxf(c2[mt][nt][3] + bv.y, 0.f) * wb;
        }
        int rl = wm * 32 + mt * 16 + lg;
        atomicAdd(&red[rl], dot0);
        atomicAdd(&red[rl + 8], dot1);
    }
    __syncthreads();
    if (tid < 128 && row0 + tid < M)
        out[row0 + tid] = red[tid] + b2[0];
}

// ---------------------------------------------------------------
extern "C" void kernel_launch(void* const* d_in, const int* in_sizes, int n_in,
                              void* d_out, int out_size) {
    const float* nf   = (const float*)d_in[0];
    const int*   src  = (const int*)d_in[1];
    const int*   dst  = (const int*)d_in[2];
    const float* Wemb = (const float*)d_in[3];
    const float* bemb = (const float*)d_in[4];
    const float* Wg   = (const float*)d_in[5];
    const float* bg   = (const float*)d_in[6];
    const float* Wo1  = (const float*)d_in[7];
    const float* bo1  = (const float*)d_in[8];
    const float* Wo2  = (const float*)d_in[9];
    const float* bo2  = (const float*)d_in[10];
    float* out = (float*)d_out;

    __half *agg, *h16;
    cudaGetSymbolAddress((void**)&agg, g_agg);
    cudaGetSymbolAddress((void**)&h16, g_h16);

    const int SM_GEMM = 2 * 128 * SW * 4;   // 69632 bytes
    cudaFuncSetAttribute(k_gemm_tc16,
                         cudaFuncAttributeMaxDynamicSharedMemorySize, SM_GEMM);
    cudaFuncSetAttribute(k_gemm3_head,
                         cudaFuncAttributeMaxDynamicSharedMemorySize, SM_GEMM);

    const int NB_EDGE2 = (NE / 2 + 255) / 256;   // 2 edges per thread
    const int NB_WARP = (NN * 32 + 255) / 256;   // warp-per-node kernels

    k_build<<<NB_EDGE2, 256>>>(src, dst);                       // 0

    k_spmm_l1<<<NB_WARP, 256>>>(nf, Wemb, bemb, agg);           // 1
    k_gemm_tc16<<<NB_TILE, 256, SM_GEMM>>>(agg, Wg, bg, h16, NN);        // 2

    k_spmm16<<<NB_WARP, 256>>>(h16, agg);                       // 3
    k_gemm_tc16<<<NB_TILE, 256, SM_GEMM>>>(agg, Wg + 128 * 128,
                                           bg + 128, h16, NN);  // 4
    k_spmm16<<<NB_WARP, 256>>>(h16, agg);                       // 5

    k_gemm3_head<<<NB_TILE, 256, SM_GEMM>>>(agg, Wg + 2 * 128 * 128,
                                            bg + 2 * 128, Wo1, bo1,
                                            Wo2, bo2, out, NN);  // 6
}